// round 3
// baseline (speedup 1.0000x reference)
#include <cuda_runtime.h>

#define NF     12
#define NCOLS  793
#define NROWS  32768
#define TPB    64           // threads per block = rows per block

// One thread per row. Combos generated by fully-unrolled nested loops so all
// s[] indices are compile-time constants (immediate-offset LDS, zero decode).
// Emissions staged through a [TPB][33] shared tile, flushed coalesced every
// 32 columns.
__global__ __launch_bounds__(TPB, 16)
void schweizer_kernel(const float* __restrict__ x,
                      const float* __restrict__ lam_p,
                      float* __restrict__ out)
{
    __shared__ float s_sh[TPB][13];
    __shared__ float buf[TPB][33];

    const int tid  = threadIdx.x;
    const int lane = tid & 31;
    const int wrp  = tid >> 5;
    const int row0 = blockIdx.x * TPB;
    const int row  = row0 + tid;

    const float lam = __ldg(lam_p);
    const float inv = 1.0f / lam;

    // This thread's row: 12 floats = 3 x float4 (row*48B is 16B-aligned)
    const float4* xr = (const float4*)(x + (size_t)row * NF);
    const float4 a = xr[0], b = xr[1], c4 = xr[2];
    const float xv[12] = {a.x, a.y, a.z, a.w,
                          b.x, b.y, b.z, b.w,
                          c4.x, c4.y, c4.z, c4.w};

    #pragma unroll
    for (int f = 0; f < NF; ++f)
        s_sh[tid][f] = 1.0f - __powf(1.0f - xv[f], lam);
    __syncthreads();

    const float* sp = s_sh[tid];

    // Coalesced flush of columns [cbase, cbase+nc)
    auto flushf = [&](int cbase) {
        __syncthreads();
        const int nc = (NCOLS - cbase < 32) ? (NCOLS - cbase) : 32;
        #pragma unroll 8
        for (int r = wrp; r < TPB; r += (TPB / 32)) {
            if (lane < nc)
                out[(size_t)(row0 + r) * NCOLS + cbase + lane] = buf[r][lane];
        }
        __syncthreads();
    };

    auto emitf = [&](int col, float v) {
        buf[tid][col & 31] = v;
        if ((col & 31) == 31 || col == NCOLS - 1) flushf(col & ~31);
    };

    // cols 0..11: passthrough of x
    #pragma unroll
    for (int f = 0; f < NF; ++f)
        emitf(f, xv[f]);

    int col = NF;

    // pairs (66) — lexicographic, matches itertools.combinations
    #pragma unroll
    for (int i = 0; i < NF - 1; ++i)
        #pragma unroll
        for (int j = i + 1; j < NF; ++j) {
            const float p = sp[i] * sp[j];
            emitf(col++, 1.0f - __powf(1.0f - p, inv));
        }

    // triples (220)
    #pragma unroll
    for (int i = 0; i < NF - 2; ++i)
        #pragma unroll
        for (int j = i + 1; j < NF - 1; ++j) {
            const float pij = sp[i] * sp[j];
            #pragma unroll
            for (int k = j + 1; k < NF; ++k) {
                const float p = pij * sp[k];
                emitf(col++, 1.0f - __powf(1.0f - p, inv));
            }
        }

    // quads (495)
    #pragma unroll
    for (int i = 0; i < NF - 3; ++i)
        #pragma unroll
        for (int j = i + 1; j < NF - 2; ++j) {
            const float pij = sp[i] * sp[j];
            #pragma unroll
            for (int k = j + 1; k < NF - 1; ++k) {
                const float pijk = pij * sp[k];
                #pragma unroll
                for (int l = k + 1; l < NF; ++l) {
                    const float p = pijk * sp[l];
                    emitf(col++, 1.0f - __powf(1.0f - p, inv));
                }
            }
        }
}

extern "C" void kernel_launch(void* const* d_in, const int* in_sizes, int n_in,
                              void* d_out, int out_size)
{
    const float* x   = (const float*)d_in[0];
    const float* lam = (const float*)d_in[1];
    float*       out = (float*)d_out;

    schweizer_kernel<<<NROWS / TPB, TPB>>>(x, lam, out);
}

// round 4
// speedup vs baseline: 3.4484x; 3.4484x over previous
#include <cuda_runtime.h>
#include <cstdint>

#define NF      12
#define NPAIR   66
#define NCOMB   781          // 66 + 220 + 495
#define NCOLS   793
#define NROWS   32768
#define RPB     8            // rows (warps) per block
#define VSTR    80           // shared row stride in floats
#define ONE_IDX 78           // val[78] = 1.0f sentinel

// pair id, lexicographic i<j
constexpr int pid(int i, int j) { return i * (2 * NF - i - 1) / 2 + (j - i - 1); }

// ---------------------------------------------------------------------------
// Combo table: each entry packs two BYTE offsets into the per-row shared
// value array val[0..78]  (val[0..11]=s_i, val[12..77]=pair products,
// val[78]=1.0).  combo value p = val[a] * val[b].
// ---------------------------------------------------------------------------
struct CTbl { uint32_t v[NCOMB]; };
struct PTbl { uint32_t v[NPAIR]; };

constexpr CTbl make_ctbl() {
    CTbl t{};
    int p = 0;
    for (int i = 0; i < NF; ++i)                       // size 2: P2 * 1
        for (int j = i + 1; j < NF; ++j)
            t.v[p++] = (uint32_t)((12 + pid(i, j)) * 4)
                     | ((uint32_t)(ONE_IDX * 4) << 16);
    for (int i = 0; i < NF; ++i)                       // size 3: P2(i,j) * s_k
        for (int j = i + 1; j < NF; ++j)
            for (int k = j + 1; k < NF; ++k)
                t.v[p++] = (uint32_t)((12 + pid(i, j)) * 4)
                         | ((uint32_t)(k * 4) << 16);
    for (int i = 0; i < NF; ++i)                       // size 4: P2(i,j)*P2(k,l)
        for (int j = i + 1; j < NF; ++j)
            for (int k = j + 1; k < NF; ++k)
                for (int l = k + 1; l < NF; ++l)
                    t.v[p++] = (uint32_t)((12 + pid(i, j)) * 4)
                             | ((uint32_t)((12 + pid(k, l)) * 4) << 16);
    return t;
}
constexpr PTbl make_ptbl() {
    PTbl t{};
    int p = 0;
    for (int i = 0; i < NF; ++i)
        for (int j = i + 1; j < NF; ++j)
            t.v[p++] = (uint32_t)i | ((uint32_t)j << 8);
    return t;
}

__device__ const CTbl d_ct = make_ctbl();
__device__ const PTbl d_pt = make_ptbl();

// ---------------------------------------------------------------------------
// Warp per row; no block-level barriers. 8 warps / block.
// ---------------------------------------------------------------------------
__global__ __launch_bounds__(256)
void schweizer_kernel(const float* __restrict__ x,
                      const float* __restrict__ lam_p,
                      float* __restrict__ out)
{
    __shared__ float val[RPB][VSTR];

    const int lane = threadIdx.x & 31;
    const int wrp  = threadIdx.x >> 5;
    const int row  = blockIdx.x * RPB + wrp;

    const float lam = __ldg(lam_p);
    const float inv = 1.0f / lam;

    float*       vrow = val[wrp];
    float*       orow = out + (size_t)row * NCOLS;
    const float* xrow = x   + (size_t)row * NF;

    // s_i and the 12 passthrough columns
    if (lane < NF) {
        const float xv = xrow[lane];
        vrow[lane] = 1.0f - __powf(1.0f - xv, lam);
        orow[lane] = xv;
    } else if (lane == NF) {
        vrow[ONE_IDX] = 1.0f;
    }
    __syncwarp();

    // 66 pairwise products
    for (int p = lane; p < NPAIR; p += 32) {
        const uint32_t w = d_pt.v[p];
        vrow[12 + p] = vrow[w & 0xFFu] * vrow[w >> 8];
    }
    __syncwarp();

    const char* vb = (const char*)vrow;
    float*      ob = orow + NF;

    #pragma unroll 5
    for (int k = 0; k < 25; ++k) {
        const int c = lane + 32 * k;
        if (c < NCOMB) {
            const uint32_t w = d_ct.v[c];
            const float a = *(const float*)(vb + (w & 0xFFFFu));
            const float b = *(const float*)(vb + (w >> 16));
            const float q = fmaf(-a, b, 1.0f);        // 1 - product
            ob[c] = 1.0f - __powf(q, inv);
        }
    }
}

extern "C" void kernel_launch(void* const* d_in, const int* in_sizes, int n_in,
                              void* d_out, int out_size)
{
    const float* x   = (const float*)d_in[0];
    const float* lam = (const float*)d_in[1];
    float*       out = (float*)d_out;

    schweizer_kernel<<<NROWS / RPB, 256>>>(x, lam, out);
}

// round 5
// speedup vs baseline: 3.6245x; 1.0511x over previous
#include <cuda_runtime.h>
#include <cstdint>

#define NF     12
#define NPAIR  66
#define NCOMB  781
#define NCOLS  793
#define NROWS  32768
#define WPB    8            // warps per block
#define RPW    4            // rows per warp
#define NVAL   80           // value slots: 12 s + 66 pairs + sentinel + pad

// pair id, lexicographic i<j
constexpr int pid(int i, int j) { return i * (2 * NF - i - 1) / 2 + (j - i - 1); }

// ---------------------------------------------------------------------------
// Combo table: two 16-bit BYTE offsets into the transposed value array
// val[NVAL][4] (16 bytes per value slot). combo p = val[a][r] * val[b][r].
// Slots: 0..11 = s_i, 12..77 = pairwise products, 78 = 1.0 sentinel.
// ---------------------------------------------------------------------------
struct CTbl { uint32_t v[NCOMB]; };
struct PTbl { uint32_t v[NPAIR]; };

constexpr CTbl make_ctbl() {
    CTbl t{};
    int p = 0;
    for (int i = 0; i < NF; ++i)                    // size 2: P2 * 1
        for (int j = i + 1; j < NF; ++j)
            t.v[p++] = (uint32_t)((12 + pid(i, j)) * 16)
                     | ((uint32_t)(78 * 16) << 16);
    for (int i = 0; i < NF; ++i)                    // size 3: P2(i,j) * s_k
        for (int j = i + 1; j < NF; ++j)
            for (int k = j + 1; k < NF; ++k)
                t.v[p++] = (uint32_t)((12 + pid(i, j)) * 16)
                         | ((uint32_t)(k * 16) << 16);
    for (int i = 0; i < NF; ++i)                    // size 4: P2(i,j) * P2(k,l)
        for (int j = i + 1; j < NF; ++j)
            for (int k = j + 1; k < NF; ++k)
                for (int l = k + 1; l < NF; ++l)
                    t.v[p++] = (uint32_t)((12 + pid(i, j)) * 16)
                             | ((uint32_t)((12 + pid(k, l)) * 16) << 16);
    return t;
}
constexpr PTbl make_ptbl() {
    PTbl t{};
    int p = 0;
    for (int i = 0; i < NF; ++i)
        for (int j = i + 1; j < NF; ++j)
            t.v[p++] = (uint32_t)i | ((uint32_t)j << 8);
    return t;
}

__device__ const CTbl d_ct = make_ctbl();
__device__ const PTbl d_pt = make_ptbl();

__device__ __forceinline__ float ss(float q, float inv) {
    return 1.0f - __powf(q, inv);
}

// ---------------------------------------------------------------------------
// Warp owns 4 rows. val transposed: val[slot][row] -> LDS.128 fetches one
// operand for all 4 rows. Table decode amortized 4x. Stores coalesced
// (lane = column), one STG.32 per row per column-group.
// ---------------------------------------------------------------------------
__global__ __launch_bounds__(256)
void schweizer_kernel(const float* __restrict__ x,
                      const float* __restrict__ lam_p,
                      float* __restrict__ out)
{
    __shared__ __align__(16) float val[WPB][NVAL][RPW];

    const int lane = threadIdx.x & 31;
    const int wrp  = threadIdx.x >> 5;
    const int r0   = (blockIdx.x * WPB + wrp) * RPW;

    const float lam = __ldg(lam_p);
    const float inv = 1.0f / lam;

    float (*v)[RPW] = val[wrp];

    // ---- prologue: s_i for 4 rows + passthrough columns -------------------
    #pragma unroll
    for (int e = lane; e < RPW * NF; e += 32) {          // 48 coalesced loads
        const float xv = x[(size_t)r0 * NF + e];
        const int f = e % NF, r = e / NF;
        v[f][r] = 1.0f - __powf(1.0f - xv, lam);
        out[(size_t)(r0 + r) * NCOLS + f] = xv;
    }
    if (lane < RPW) v[78][lane] = 1.0f;                  // sentinel
    __syncwarp();

    // ---- 66 pairwise products (vectorized over 4 rows) ---------------------
    #pragma unroll
    for (int p = lane; p < NPAIR; p += 32) {
        const uint32_t w = d_pt.v[p];
        const float4 a = *(const float4*)v[w & 0xFFu];
        const float4 b = *(const float4*)v[w >> 8];
        float4 r4;
        r4.x = a.x * b.x;  r4.y = a.y * b.y;
        r4.z = a.z * b.z;  r4.w = a.w * b.w;
        *(float4*)v[12 + p] = r4;
    }
    __syncwarp();

    // ---- main sweep: 24 full groups of 32 columns + 13-column tail ---------
    const char* vb = (const char*)v;
    float*      ob = out + (size_t)r0 * NCOLS + NF;

    #pragma unroll 6
    for (int k = 0; k < 24; ++k) {
        const int c = k * 32 + lane;
        const uint32_t w = d_ct.v[c];
        const float4 a = *(const float4*)(vb + (w & 0xFFFFu));
        const float4 b = *(const float4*)(vb + (w >> 16));
        ob[c]             = ss(fmaf(-a.x, b.x, 1.0f), inv);
        ob[c + NCOLS]     = ss(fmaf(-a.y, b.y, 1.0f), inv);
        ob[c + 2 * NCOLS] = ss(fmaf(-a.z, b.z, 1.0f), inv);
        ob[c + 3 * NCOLS] = ss(fmaf(-a.w, b.w, 1.0f), inv);
    }
    if (lane < NCOMB - 768) {                            // cols 768..780
        const int c = 768 + lane;
        const uint32_t w = d_ct.v[c];
        const float4 a = *(const float4*)(vb + (w & 0xFFFFu));
        const float4 b = *(const float4*)(vb + (w >> 16));
        ob[c]             = ss(fmaf(-a.x, b.x, 1.0f), inv);
        ob[c + NCOLS]     = ss(fmaf(-a.y, b.y, 1.0f), inv);
        ob[c + 2 * NCOLS] = ss(fmaf(-a.z, b.z, 1.0f), inv);
        ob[c + 3 * NCOLS] = ss(fmaf(-a.w, b.w, 1.0f), inv);
    }
}

extern "C" void kernel_launch(void* const* d_in, const int* in_sizes, int n_in,
                              void* d_out, int out_size)
{
    const float* x   = (const float*)d_in[0];
    const float* lam = (const float*)d_in[1];
    float*       out = (float*)d_out;

    schweizer_kernel<<<NROWS / (WPB * RPW), 256>>>(x, lam, out);
}